// round 12
// baseline (speedup 1.0000x reference)
#include <cuda_runtime.h>
#include <cuda_fp16.h>
#include <cstdint>

// Problem dims
#define Bn 16
#define Cc 128
#define Hh 128
#define Wd 128
#define Oo 256

#define FXC 835.5924988699915f    // 4096*sqrt(1/24) - 0.5
#define FWC 20017.230178024133f   // 4096*sqrt(24) - 5*sqrt(96)

// ---------------- device globals -------------------------------------------
__device__ unsigned int g_xmax_bits;      // static-zero; atomicMax is idempotent
__device__ float g_fw[Oo];
__device__ __half g_wqh[Oo * Cc * 9];     // [oc][ic][tap]
// A fragments, HMMA m16n8k16 per-lane layout (with ic->k permutation):
// idx = ((((oh*8+ck)*9+tap)*8 + mt)*32 + lane)*4 + reg
__device__ uint32_t g_wfrag[2 * 8 * 9 * 8 * 32 * 4];
// quantized input, TRANSPOSED: [n][h][w][ic], ic contiguous
__device__ __half g_xqT[(size_t)Bn * Hh * Wd * Cc];

// ---------------- kernel 1: xmax (blocks 0..1023) + weight prep (1024..1279)
__global__ void __launch_bounds__(256)
k1_xmax_prep(const float4* __restrict__ x, int n4, const float* __restrict__ Wt) {
    const int tid = threadIdx.x;
    const int lane = tid & 31, wid = tid >> 5;
    if (blockIdx.x < 1024) {
        float m = 0.f;
        for (int i = blockIdx.x * 256 + tid; i < n4; i += 1024 * 256) {
            float4 v = x[i];
            m = fmaxf(m, fmaxf(fmaxf(fabsf(v.x), fabsf(v.y)),
                               fmaxf(fabsf(v.z), fabsf(v.w))));
        }
#pragma unroll
        for (int o = 16; o; o >>= 1) m = fmaxf(m, __shfl_xor_sync(0xffffffffu, m, o));
        __shared__ float sm[8];
        if (lane == 0) sm[wid] = m;
        __syncthreads();
        if (wid == 0) {
            m = (lane < 8) ? sm[lane] : 0.f;
#pragma unroll
            for (int o = 4; o; o >>= 1) m = fmaxf(m, __shfl_xor_sync(0xffffffffu, m, o));
            if (lane == 0) atomicMax(&g_xmax_bits, __float_as_uint(m));
        }
    } else {
        const int oc = blockIdx.x - 1024;
        __shared__ float s_red[4];
        __shared__ float s_fw;
        float w9[9];
        float s = 0.f;
        if (tid < 128) {
            const float* wr = Wt + (size_t)oc * 1152 + tid * 9;
#pragma unroll
            for (int i = 0; i < 9; i++) { w9[i] = wr[i]; s += fabsf(w9[i]); }
#pragma unroll
            for (int o = 16; o; o >>= 1) s += __shfl_xor_sync(0xffffffffu, s, o);
            if (lane == 0) s_red[wid] = s;
        }
        __syncthreads();
        if (tid == 0) {
            float ws = s_red[0] + s_red[1] + s_red[2] + s_red[3];
            if (ws == 0.f) ws = 1.f;
            float fw = FWC / ws;
            g_fw[oc] = fw;
            s_fw = fw;
        }
        __syncthreads();
        if (tid < 128) {
            const float fw = s_fw;
#pragma unroll
            for (int i = 0; i < 9; i++)
                g_wqh[(oc * 128 + tid) * 9 + i] = __float2half_rn(rintf(w9[i] * fw));
        }
    }
}

// ---------------- kernel 2: x quantize->f16 transposed + A pack -------------
// blocks 0..2047: one (n,h) slab each -> g_xqT[n][h][w][ic]
// blocks 2048.. : pack A fragments with the ic->k permutation
__global__ void __launch_bounds__(256)
k2_xq_pack(const float* __restrict__ xf) {
    const int tid = threadIdx.x;
    if (blockIdx.x < 2048) {
        __shared__ __half s[128 * 136];   // [w][ic], pad 136
        const int n = blockIdx.x >> 7;
        const int h = blockIdx.x & 127;
        const float x_max = __uint_as_float(g_xmax_bits);
        const float fx = (x_max > 0.f) ? FXC / x_max : 1.0f;

        // load: thread = (ic, w-half); 16 x float4 along w
        {
            const int ic = tid >> 1;
            const int wh = (tid & 1) * 64;
            const float4* src = reinterpret_cast<const float4*>(
                xf + (((size_t)n * Cc + ic) * Hh + h) * Wd + wh);
#pragma unroll
            for (int i = 0; i < 16; i++) {
                float4 v = __ldg(&src[i]);
                const int w = wh + i * 4;
                s[(w + 0) * 136 + ic] = __float2half_rn(rintf(fx * v.x));
                s[(w + 1) * 136 + ic] = __float2half_rn(rintf(fx * v.y));
                s[(w + 2) * 136 + ic] = __float2half_rn(rintf(fx * v.z));
                s[(w + 3) * 136 + ic] = __float2half_rn(rintf(fx * v.w));
            }
        }
        __syncthreads();
        // store: thread = (w, ic-half); 8 x uint4 contiguous
        {
            const int w = tid >> 1;
            const int ich = (tid & 1) * 64;
            const uint4* sv = reinterpret_cast<const uint4*>(&s[w * 136 + ich]);
            uint4* dst = reinterpret_cast<uint4*>(
                g_xqT + (((size_t)n * Hh + h) * Wd + w) * Cc + ich);
#pragma unroll
            for (int i = 0; i < 8; i++) dst[i] = sv[i];
        }
    } else {
        int gid = (blockIdx.x - 2048) * 256 + tid;
        if (gid >= 2 * 8 * 9 * 8 * 32 * 4) return;
        int tmp = gid;
        const int r = tmp & 3;   tmp >>= 2;
        const int l = tmp & 31;  tmp >>= 5;
        const int mt = tmp & 7;  tmp >>= 3;
        const int tap = tmp % 9; tmp /= 9;
        const int ck = tmp & 7;  tmp >>= 3;
        const int oh = tmp;
        const int m = (l >> 2) + (r & 1) * 8;
        // permuted k: k pair (r>>1) of lane group s=l&3 comes from ic 4s + 2*(r>>1)
        const int kk = 4 * (l & 3) + (r >> 1) * 2;
        const int oc = oh * 128 + mt * 16 + m;
        const int ic = ck * 16 + kk;
        __half2 p = __halves2half2(g_wqh[(oc * 128 + ic) * 9 + tap],
                                   g_wqh[(oc * 128 + ic + 1) * 9 + tap]);
        g_wfrag[gid] = *reinterpret_cast<uint32_t*>(&p);
    }
}

// ---------------- kernel: dummy (ncu capture alignment) ---------------------
__global__ void k_dummy() {}

// ---------------- HMMA helper ----------------------------------------------
static __device__ __forceinline__ void mma16816(float* c, const uint32_t* a,
                                                uint32_t b0, uint32_t b1) {
    asm volatile(
        "mma.sync.aligned.m16n8k16.row.col.f32.f16.f16.f32 "
        "{%0,%1,%2,%3}, {%4,%5,%6,%7}, {%8,%9}, {%0,%1,%2,%3};"
        : "+f"(c[0]), "+f"(c[1]), "+f"(c[2]), "+f"(c[3])
        : "r"(a[0]), "r"(a[1]), "r"(a[2]), "r"(a[3]), "r"(b0), "r"(b1));
}

// ---------------- kernel 3: conv (no smem staging, direct-LDG B) ------------
// grid (2 ochalf, 64 hpair, 16 n); 256 threads (8 warps).
// warp: 64 oc x (1 h x 64 w). B fragment = 1 predicated LDG.64 per lane.
__global__ void __launch_bounds__(256)
conv_kernel(const float* __restrict__ bias, float* __restrict__ out) {
    __shared__ float s_inv[128], s_b[128];

    const int oh = blockIdx.x;
    const int hbase = blockIdx.y * 2;
    const int n_img = blockIdx.z;
    const int tid = threadIdx.x;
    const int l = tid & 31;
    const int ww = tid >> 5;
    const int warp_m = ww >> 2;
    const int warp_n = ww & 3;
    const int h = hbase + (warp_n >> 1);
    const int wbase = (warp_n & 1) * 64;

    const float x_max = __uint_as_float(g_xmax_bits);
    const float fx = (x_max > 0.f) ? FXC / x_max : 1.0f;

    if (tid < 128) {
        s_inv[tid] = 1.0f / (fx * g_fw[oh * 128 + tid]);
        s_b[tid] = __ldg(&bias[oh * 128 + tid]);
    }

    float acc[4][8][4];
#pragma unroll
    for (int a = 0; a < 4; a++)
#pragma unroll
        for (int b = 0; b < 8; b++)
#pragma unroll
            for (int c = 0; c < 4; c++) acc[a][b][c] = 0.f;

    // lane-invariant parts of the B address
    const __half* xT = g_xqT + (size_t)n_img * Hh * Wd * Cc;
    const int wlane = wbase + (l >> 2);      // + nt*8 + kw - 1 later
    const int icl = 4 * (l & 3);             // ic offset within chunk

    const uint4* wf = reinterpret_cast<const uint4*>(g_wfrag);

    for (int ck = 0; ck < 8; ck++) {
        const int icc = ck * 16 + icl;

        // ---- B loader (per tap): 8 predicated LDG.64
        uint2 bbuf[2][8];
        {
            // tap 0: kh=0, kw=0
            const int hx = h - 1;
            const bool vh = hx >= 0;
            const __half* rowp = xT + ((size_t)hx * Wd) * Cc + icc;
#pragma unroll
            for (int nt = 0; nt < 8; nt++) {
                const int wx = wlane + nt * 8 - 1;
                bbuf[0][nt] = (vh && (unsigned)wx < (unsigned)Wd)
                                  ? __ldg(reinterpret_cast<const uint2*>(rowp + (size_t)wx * Cc))
                                  : make_uint2(0u, 0u);
            }
        }
        // ---- A tap-0 fragments
        uint4 a_buf[2][4];
        {
            const int tile0 = ((oh * 8 + ck) * 9 + 0) * 8 + warp_m * 4;
#pragma unroll
            for (int mt = 0; mt < 4; mt++)
                a_buf[0][mt] = __ldg(&wf[(tile0 + mt) * 32 + l]);
        }

#pragma unroll
        for (int tap = 0; tap < 9; tap++) {
            const int cur = tap & 1;
            if (tap < 8) {
                // prefetch next tap's A
                const int tileN = ((oh * 8 + ck) * 9 + tap + 1) * 8 + warp_m * 4;
#pragma unroll
                for (int mt = 0; mt < 4; mt++)
                    a_buf[cur ^ 1][mt] = __ldg(&wf[(tileN + mt) * 32 + l]);
                // prefetch next tap's B
                const int tnext = tap + 1;
                const int kh = tnext / 3, kw = tnext - kh * 3;
                const int hx = h + kh - 1;
                const bool vh = (unsigned)hx < (unsigned)Hh;
                const __half* rowp = xT + ((size_t)hx * Wd) * Cc + icc;
                const int wsh = wlane + kw - 1;
#pragma unroll
                for (int nt = 0; nt < 8; nt++) {
                    const int wx = wsh + nt * 8;
                    bbuf[cur ^ 1][nt] =
                        (vh && (unsigned)wx < (unsigned)Wd)
                            ? __ldg(reinterpret_cast<const uint2*>(rowp + (size_t)wx * Cc))
                            : make_uint2(0u, 0u);
                }
            }
#pragma unroll
            for (int nt = 0; nt < 8; nt++) {
                const uint32_t b0 = bbuf[cur][nt].x;
                const uint32_t b1 = bbuf[cur][nt].y;
#pragma unroll
                for (int mt = 0; mt < 4; mt++)
                    mma16816(acc[mt][nt],
                             reinterpret_cast<const uint32_t*>(&a_buf[cur][mt]),
                             b0, b1);
            }
        }
    }

    __syncthreads();   // s_inv / s_b visibility

    // ---- epilogue: dequant + bias + relu, float2 stores ----
#pragma unroll
    for (int mt = 0; mt < 4; mt++) {
#pragma unroll
        for (int r2 = 0; r2 < 2; r2++) {
            const int ocl = warp_m * 64 + mt * 16 + (l >> 2) + r2 * 8;
            const float inv = s_inv[ocl];
            const float bv = s_b[ocl];
            float* orow =
                out + (((size_t)n_img * Oo + oh * 128 + ocl) * Hh + h) * Wd;
#pragma unroll
            for (int nt = 0; nt < 8; nt++) {
                const int w = wbase + nt * 8 + 2 * (l & 3);
                float2 o2;
                o2.x = fmaxf(fmaf(acc[mt][nt][r2 * 2], inv, bv), 0.f);
                o2.y = fmaxf(fmaf(acc[mt][nt][r2 * 2 + 1], inv, bv), 0.f);
                *reinterpret_cast<float2*>(&orow[w]) = o2;
            }
        }
    }
}

// ---------------- launch ----------------------------------------------------
extern "C" void kernel_launch(void* const* d_in, const int* in_sizes, int n_in,
                              void* d_out, int out_size) {
    const float* x = (const float*)d_in[0];   // [16,128,128,128]
    const float* Wt = (const float*)d_in[1];  // [256,128,3,3]
    const float* b = (const float*)d_in[2];   // [256]
    float* out = (float*)d_out;               // [16,256,128,128]

    const int n4 = (Bn * Cc * Hh * Wd) / 4;
    k1_xmax_prep<<<1024 + Oo, 256>>>((const float4*)x, n4, Wt);
    k2_xq_pack<<<2048 + 576, 256>>>(x);
    dim3 grid(2, 64, Bn);
    conv_kernel<<<grid, 256>>>(b, out);
    k_dummy<<<1, 32>>>();
}

// round 14
// speedup vs baseline: 1.2634x; 1.2634x over previous
#include <cuda_runtime.h>
#include <cuda_fp16.h>
#include <cstdint>

// Problem dims
#define Bn 16
#define Cc 128
#define Hh 128
#define Wd 128
#define Oo 256

#define FXC 835.5924988699915f    // 4096*sqrt(1/24) - 0.5
#define FWC 20017.230178024133f   // 4096*sqrt(24) - 5*sqrt(96)

// ---------------- device globals -------------------------------------------
__device__ unsigned int g_xmax_bits;      // static-zero; atomicMax is idempotent
__device__ float g_fw[Oo];
__device__ __half g_wqh[Oo * Cc * 9];     // [oc][ic][tap]
// A fragments, HMMA m16n8k16 per-lane layout (with ic->k permutation):
// idx = ((((oh*8+ck)*9+tap)*8 + mt)*32 + lane)*4 + reg
__device__ uint32_t g_wfrag[2 * 8 * 9 * 8 * 32 * 4];
// quantized input, TRANSPOSED: [n][h][w][ic], ic contiguous
__device__ __half g_xqT[(size_t)Bn * Hh * Wd * Cc];

// ---------------- kernel 1: xmax (blocks 0..1023) + weight prep (1024..1279)
__global__ void __launch_bounds__(256)
k1_xmax_prep(const float4* __restrict__ x, int n4, const float* __restrict__ Wt) {
    const int tid = threadIdx.x;
    const int lane = tid & 31, wid = tid >> 5;
    if (blockIdx.x < 1024) {
        float m = 0.f;
        for (int i = blockIdx.x * 256 + tid; i < n4; i += 1024 * 256) {
            float4 v = x[i];
            m = fmaxf(m, fmaxf(fmaxf(fabsf(v.x), fabsf(v.y)),
                               fmaxf(fabsf(v.z), fabsf(v.w))));
        }
#pragma unroll
        for (int o = 16; o; o >>= 1) m = fmaxf(m, __shfl_xor_sync(0xffffffffu, m, o));
        __shared__ float sm[8];
        if (lane == 0) sm[wid] = m;
        __syncthreads();
        if (wid == 0) {
            m = (lane < 8) ? sm[lane] : 0.f;
#pragma unroll
            for (int o = 4; o; o >>= 1) m = fmaxf(m, __shfl_xor_sync(0xffffffffu, m, o));
            if (lane == 0) atomicMax(&g_xmax_bits, __float_as_uint(m));
        }
    } else {
        const int oc = blockIdx.x - 1024;
        __shared__ float s_red[4];
        __shared__ float s_fw;
        float w9[9];
        float s = 0.f;
        if (tid < 128) {
            const float* wr = Wt + (size_t)oc * 1152 + tid * 9;
#pragma unroll
            for (int i = 0; i < 9; i++) { w9[i] = wr[i]; s += fabsf(w9[i]); }
#pragma unroll
            for (int o = 16; o; o >>= 1) s += __shfl_xor_sync(0xffffffffu, s, o);
            if (lane == 0) s_red[wid] = s;
        }
        __syncthreads();
        if (tid == 0) {
            float ws = s_red[0] + s_red[1] + s_red[2] + s_red[3];
            if (ws == 0.f) ws = 1.f;
            float fw = FWC / ws;
            g_fw[oc] = fw;
            s_fw = fw;
        }
        __syncthreads();
        if (tid < 128) {
            const float fw = s_fw;
#pragma unroll
            for (int i = 0; i < 9; i++)
                g_wqh[(oc * 128 + tid) * 9 + i] = __float2half_rn(rintf(w9[i] * fw));
        }
    }
}

// ---------------- kernel 2: x quantize->f16 transposed + A pack -------------
// blocks 0..2047: one (n,h) slab each -> g_xqT[n][h][w][ic]
// blocks 2048.. : pack A fragments with the ic->k permutation
__global__ void __launch_bounds__(256)
k2_xq_pack(const float* __restrict__ xf) {
    const int tid = threadIdx.x;
    if (blockIdx.x < 2048) {
        __shared__ __half s[128 * 136];   // [w][ic], pad 136
        const int n = blockIdx.x >> 7;
        const int h = blockIdx.x & 127;
        const float x_max = __uint_as_float(g_xmax_bits);
        const float fx = (x_max > 0.f) ? FXC / x_max : 1.0f;

        // load: thread = (ic, w-half); 16 x float4 along w
        {
            const int ic = tid >> 1;
            const int wh = (tid & 1) * 64;
            const float4* src = reinterpret_cast<const float4*>(
                xf + (((size_t)n * Cc + ic) * Hh + h) * Wd + wh);
#pragma unroll
            for (int i = 0; i < 16; i++) {
                float4 v = __ldg(&src[i]);
                const int w = wh + i * 4;
                s[(w + 0) * 136 + ic] = __float2half_rn(rintf(fx * v.x));
                s[(w + 1) * 136 + ic] = __float2half_rn(rintf(fx * v.y));
                s[(w + 2) * 136 + ic] = __float2half_rn(rintf(fx * v.z));
                s[(w + 3) * 136 + ic] = __float2half_rn(rintf(fx * v.w));
            }
        }
        __syncthreads();
        // store: thread = (w, ic-half); 8 x uint4 contiguous
        {
            const int w = tid >> 1;
            const int ich = (tid & 1) * 64;
            const uint4* sv = reinterpret_cast<const uint4*>(&s[w * 136 + ich]);
            uint4* dst = reinterpret_cast<uint4*>(
                g_xqT + (((size_t)n * Hh + h) * Wd + w) * Cc + ich);
#pragma unroll
            for (int i = 0; i < 8; i++) dst[i] = sv[i];
        }
    } else {
        int gid = (blockIdx.x - 2048) * 256 + tid;
        if (gid >= 2 * 8 * 9 * 8 * 32 * 4) return;
        int tmp = gid;
        const int r = tmp & 3;   tmp >>= 2;
        const int l = tmp & 31;  tmp >>= 5;
        const int mt = tmp & 7;  tmp >>= 3;
        const int tap = tmp % 9; tmp /= 9;
        const int ck = tmp & 7;  tmp >>= 3;
        const int oh = tmp;
        const int m = (l >> 2) + (r & 1) * 8;
        // permuted k: k pair (r>>1) of lane group s=l&3 comes from ic 4s + 2*(r>>1)
        const int kk = 4 * (l & 3) + (r >> 1) * 2;
        const int oc = oh * 128 + mt * 16 + m;
        const int ic = ck * 16 + kk;
        __half2 p = __halves2half2(g_wqh[(oc * 128 + ic) * 9 + tap],
                                   g_wqh[(oc * 128 + ic + 1) * 9 + tap]);
        g_wfrag[gid] = *reinterpret_cast<uint32_t*>(&p);
    }
}

// ---------------- kernel: dummy (ncu capture alignment: conv = launch #4) ---
__global__ void k_dummy() {}

// ---------------- HMMA helper ----------------------------------------------
static __device__ __forceinline__ void mma16816(float* c, const uint32_t* a,
                                                uint32_t b0, uint32_t b1) {
    asm volatile(
        "mma.sync.aligned.m16n8k16.row.col.f32.f16.f16.f32 "
        "{%0,%1,%2,%3}, {%4,%5,%6,%7}, {%8,%9}, {%0,%1,%2,%3};"
        : "+f"(c[0]), "+f"(c[1]), "+f"(c[2]), "+f"(c[3])
        : "r"(a[0]), "r"(a[1]), "r"(a[2]), "r"(a[3]), "r"(b0), "r"(b1));
}

// ---------------- kernel 3: conv (vectorized smem staging from g_xqT) -------
// grid (2 ochalf, 64 hpair, 16 n); 256 threads (8 warps).
// smem buffer: [4 rows][130 widx][16 ic] halves; widx = w+1.
// Staging per chunk per thread: 4 predicated LDG.128 + 4 STS.128.
#define ROWH (130 * 16)               // halves per row
#define BUF_H (4 * ROWH)              // halves per buffer

__global__ void __launch_bounds__(256)
conv_kernel(const float* __restrict__ bias, float* __restrict__ out) {
    __shared__ __half sB[2 * BUF_H];
    __shared__ float s_inv[128], s_b[128];

    const int oh = blockIdx.x;
    const int hbase = blockIdx.y * 2;
    const int n_img = blockIdx.z;
    const int tid = threadIdx.x;
    const int l = tid & 31;
    const int ww = tid >> 5;
    const int warp_m = ww >> 2;
    const int warp_n = ww & 3;
    const int h_sub = warp_n >> 1;
    const int wbase = (warp_n & 1) * 64;

    const float x_max = __uint_as_float(g_xmax_bits);
    const float fx = (x_max > 0.f) ? FXC / x_max : 1.0f;

    // zero both buffers once (w-padding + OOB rows stay zero for all chunks)
    {
        uint4* z = reinterpret_cast<uint4*>(sB);
        const int n16 = (2 * BUF_H * 2) / 16;
        for (int i = tid; i < n16; i += 256) z[i] = make_uint4(0, 0, 0, 0);
    }
    if (tid < 128) {
        s_inv[tid] = 1.0f / (fx * g_fw[oh * 128 + tid]);
        s_b[tid] = __ldg(&bias[oh * 128 + tid]);
    }

    float acc[4][8][4];
#pragma unroll
    for (int a = 0; a < 4; a++)
#pragma unroll
        for (int b = 0; b < 8; b++)
#pragma unroll
            for (int c = 0; c < 4; c++) acc[a][b][c] = 0.f;

    const __half* xT = g_xqT + (size_t)n_img * Hh * Wd * Cc;
    // staging coords: thread -> (w, ich); row = unroll index
    const int st_w = tid >> 1;
    const int st_ich = (tid & 1) * 8;             // ic offset in halves
    const __half* st_g = xT + ((size_t)(hbase - 1) * Wd + st_w) * Cc + st_ich;
    __half* st_s = sB + ((st_w + 1) * 16 + st_ich);
    bool rowok[4];
#pragma unroll
    for (int r4 = 0; r4 < 4; r4++)
        rowok[r4] = (unsigned)(hbase + r4 - 1) < (unsigned)Hh;

    const uint4* wf = reinterpret_cast<const uint4*>(g_wfrag);

    __syncthreads();
    // stage chunk 0 into buffer 0
    {
        uint4 pf[4];
#pragma unroll
        for (int r4 = 0; r4 < 4; r4++)
            if (rowok[r4])
                pf[r4] = *reinterpret_cast<const uint4*>(st_g + (size_t)r4 * Hh * Wd * 0 + (size_t)r4 * Wd * Cc);
#pragma unroll
        for (int r4 = 0; r4 < 4; r4++)
            if (rowok[r4])
                *reinterpret_cast<uint4*>(st_s + r4 * ROWH) = pf[r4];
    }
    __syncthreads();

    for (int ck = 0; ck < 8; ck++) {
        const int cur = ck & 1;
        const __half* sbuf = sB + cur * BUF_H;

        // prefetch next chunk's x into registers (hidden behind MMA)
        uint4 pf[4];
        if (ck < 7) {
            const __half* gsrc = st_g + (ck + 1) * 16;
#pragma unroll
            for (int r4 = 0; r4 < 4; r4++)
                if (rowok[r4])
                    pf[r4] = *reinterpret_cast<const uint4*>(gsrc + (size_t)r4 * Wd * Cc);
        }

        // A-fragment double buffer (tap-level prefetch)
        uint4 a_buf[2][4];
        {
            const int tile0 = ((oh * 8 + ck) * 9 + 0) * 8 + warp_m * 4;
#pragma unroll
            for (int mt = 0; mt < 4; mt++)
                a_buf[0][mt] = __ldg(&wf[(tile0 + mt) * 32 + l]);
        }
#pragma unroll
        for (int tap = 0; tap < 9; tap++) {
            const int curA = tap & 1;
            if (tap < 8) {
                const int tileN = ((oh * 8 + ck) * 9 + tap + 1) * 8 + warp_m * 4;
#pragma unroll
                for (int mt = 0; mt < 4; mt++)
                    a_buf[curA ^ 1][mt] = __ldg(&wf[(tileN + mt) * 32 + l]);
            }
            const int kh = tap / 3, kw = tap - kh * 3;
            const int row4 = h_sub + kh;
            const int widx = wbase + (l >> 2) + kw;     // w+1 handled: widx = w - 1 + kw + 1
            const __half* bp0 = sbuf + (row4 * 130 + widx) * 16 + 4 * (l & 3);
#pragma unroll
            for (int nt = 0; nt < 8; nt++) {
                const uint2 bv = *reinterpret_cast<const uint2*>(bp0 + nt * 8 * 16);
#pragma unroll
                for (int mt = 0; mt < 4; mt++)
                    mma16816(acc[mt][nt],
                             reinterpret_cast<const uint32_t*>(&a_buf[curA][mt]),
                             bv.x, bv.y);
            }
        }

        if (ck < 7) {
            __half* sdst = sB + (cur ^ 1) * BUF_H + ((st_w + 1) * 16 + st_ich);
#pragma unroll
            for (int r4 = 0; r4 < 4; r4++)
                if (rowok[r4])
                    *reinterpret_cast<uint4*>(sdst + r4 * ROWH) = pf[r4];
        }
        __syncthreads();
    }

    // ---- epilogue: dequant + bias + relu, float2 stores ----
    const int h = hbase + h_sub;
#pragma unroll
    for (int mt = 0; mt < 4; mt++) {
#pragma unroll
        for (int r2 = 0; r2 < 2; r2++) {
            const int ocl = warp_m * 64 + mt * 16 + (l >> 2) + r2 * 8;
            const float inv = s_inv[ocl];
            const float bv = s_b[ocl];
            float* orow =
                out + (((size_t)n_img * Oo + oh * 128 + ocl) * Hh + h) * Wd;
#pragma unroll
            for (int nt = 0; nt < 8; nt++) {
                const int w = wbase + nt * 8 + 2 * (l & 3);
                float2 o2;
                o2.x = fmaxf(fmaf(acc[mt][nt][r2 * 2], inv, bv), 0.f);
                o2.y = fmaxf(fmaf(acc[mt][nt][r2 * 2 + 1], inv, bv), 0.f);
                *reinterpret_cast<float2*>(&orow[w]) = o2;
            }
        }
    }
}

// ---------------- launch ----------------------------------------------------
extern "C" void kernel_launch(void* const* d_in, const int* in_sizes, int n_in,
                              void* d_out, int out_size) {
    const float* x = (const float*)d_in[0];   // [16,128,128,128]
    const float* Wt = (const float*)d_in[1];  // [256,128,3,3]
    const float* b = (const float*)d_in[2];   // [256]
    float* out = (float*)d_out;               // [16,256,128,128]

    const int n4 = (Bn * Cc * Hh * Wd) / 4;
    k1_xmax_prep<<<1024 + Oo, 256>>>((const float4*)x, n4, Wt);
    k2_xq_pack<<<2048 + 576, 256>>>(x);
    k_dummy<<<1, 32>>>();
    dim3 grid(2, 64, Bn);
    conv_kernel<<<grid, 256>>>(b, out);
}

// round 16
// speedup vs baseline: 1.3495x; 1.0681x over previous
#include <cuda_runtime.h>
#include <cuda_fp16.h>
#include <cstdint>

// Problem dims
#define Bn 16
#define Cc 128
#define Hh 128
#define Wd 128
#define Oo 256

#define FXC 835.5924988699915f    // 4096*sqrt(1/24) - 0.5
#define FWC 20017.230178024133f   // 4096*sqrt(24) - 5*sqrt(96)

// ---------------- device globals -------------------------------------------
__device__ unsigned int g_xmax_bits;      // static-zero; atomicMax is idempotent
__device__ float g_fw[Oo];
__device__ __half g_wqh[Oo * Cc * 9];     // [oc][ic][tap]
// A fragments, HMMA m16n8k16 per-lane layout (with ic->k permutation):
// idx = ((((oh*8+ck)*9+tap)*8 + mtg)*32 + lane)*4 + reg
__device__ uint32_t g_wfrag[2 * 8 * 9 * 8 * 32 * 4];
// quantized input, TRANSPOSED: [n][h][w][ic], ic contiguous
__device__ __half g_xqT[(size_t)Bn * Hh * Wd * Cc];

// ---------------- kernel 1: xmax (blocks 0..1023) + weight prep (1024..1279)
__global__ void __launch_bounds__(256)
k1_xmax_prep(const float4* __restrict__ x, int n4, const float* __restrict__ Wt) {
    const int tid = threadIdx.x;
    const int lane = tid & 31, wid = tid >> 5;
    if (blockIdx.x < 1024) {
        float m = 0.f;
        for (int i = blockIdx.x * 256 + tid; i < n4; i += 1024 * 256) {
            float4 v = x[i];
            m = fmaxf(m, fmaxf(fmaxf(fabsf(v.x), fabsf(v.y)),
                               fmaxf(fabsf(v.z), fabsf(v.w))));
        }
#pragma unroll
        for (int o = 16; o; o >>= 1) m = fmaxf(m, __shfl_xor_sync(0xffffffffu, m, o));
        __shared__ float sm[8];
        if (lane == 0) sm[wid] = m;
        __syncthreads();
        if (wid == 0) {
            m = (lane < 8) ? sm[lane] : 0.f;
#pragma unroll
            for (int o = 4; o; o >>= 1) m = fmaxf(m, __shfl_xor_sync(0xffffffffu, m, o));
            if (lane == 0) atomicMax(&g_xmax_bits, __float_as_uint(m));
        }
    } else {
        const int oc = blockIdx.x - 1024;
        __shared__ float s_red[4];
        __shared__ float s_fw;
        float w9[9];
        float s = 0.f;
        if (tid < 128) {
            const float* wr = Wt + (size_t)oc * 1152 + tid * 9;
#pragma unroll
            for (int i = 0; i < 9; i++) { w9[i] = wr[i]; s += fabsf(w9[i]); }
#pragma unroll
            for (int o = 16; o; o >>= 1) s += __shfl_xor_sync(0xffffffffu, s, o);
            if (lane == 0) s_red[wid] = s;
        }
        __syncthreads();
        if (tid == 0) {
            float ws = s_red[0] + s_red[1] + s_red[2] + s_red[3];
            if (ws == 0.f) ws = 1.f;
            float fw = FWC / ws;
            g_fw[oc] = fw;
            s_fw = fw;
        }
        __syncthreads();
        if (tid < 128) {
            const float fw = s_fw;
#pragma unroll
            for (int i = 0; i < 9; i++)
                g_wqh[(oc * 128 + tid) * 9 + i] = __float2half_rn(rintf(w9[i] * fw));
        }
    }
}

// ---------------- kernel 2: x quantize->f16 transposed + A pack -------------
__global__ void __launch_bounds__(256)
k2_xq_pack(const float* __restrict__ xf) {
    const int tid = threadIdx.x;
    if (blockIdx.x < 2048) {
        __shared__ __half s[128 * 136];   // [w][ic], pad 136
        const int n = blockIdx.x >> 7;
        const int h = blockIdx.x & 127;
        const float x_max = __uint_as_float(g_xmax_bits);
        const float fx = (x_max > 0.f) ? FXC / x_max : 1.0f;
        {
            const int ic = tid >> 1;
            const int wh = (tid & 1) * 64;
            const float4* src = reinterpret_cast<const float4*>(
                xf + (((size_t)n * Cc + ic) * Hh + h) * Wd + wh);
#pragma unroll
            for (int i = 0; i < 16; i++) {
                float4 v = __ldg(&src[i]);
                const int w = wh + i * 4;
                s[(w + 0) * 136 + ic] = __float2half_rn(rintf(fx * v.x));
                s[(w + 1) * 136 + ic] = __float2half_rn(rintf(fx * v.y));
                s[(w + 2) * 136 + ic] = __float2half_rn(rintf(fx * v.z));
                s[(w + 3) * 136 + ic] = __float2half_rn(rintf(fx * v.w));
            }
        }
        __syncthreads();
        {
            const int w = tid >> 1;
            const int ich = (tid & 1) * 64;
            const uint4* sv = reinterpret_cast<const uint4*>(&s[w * 136 + ich]);
            uint4* dst = reinterpret_cast<uint4*>(
                g_xqT + (((size_t)n * Hh + h) * Wd + w) * Cc + ich);
#pragma unroll
            for (int i = 0; i < 8; i++) dst[i] = sv[i];
        }
    } else {
        int gid = (blockIdx.x - 2048) * 256 + tid;
        if (gid >= 2 * 8 * 9 * 8 * 32 * 4) return;
        int tmp = gid;
        const int r = tmp & 3;   tmp >>= 2;
        const int l = tmp & 31;  tmp >>= 5;
        const int mt = tmp & 7;  tmp >>= 3;
        const int tap = tmp % 9; tmp /= 9;
        const int ck = tmp & 7;  tmp >>= 3;
        const int oh = tmp;
        const int m = (l >> 2) + (r & 1) * 8;
        const int kk = 4 * (l & 3) + (r >> 1) * 2;
        const int oc = oh * 128 + mt * 16 + m;
        const int ic = ck * 16 + kk;
        __half2 p = __halves2half2(g_wqh[(oc * 128 + ic) * 9 + tap],
                                   g_wqh[(oc * 128 + ic + 1) * 9 + tap]);
        g_wfrag[gid] = *reinterpret_cast<uint32_t*>(&p);
    }
}

// ---------------- kernel: dummy (ncu capture alignment: conv = launch #4) ---
__global__ void k_dummy() {}

// ---------------- HMMA helper ----------------------------------------------
static __device__ __forceinline__ void mma16816(float* c, const uint32_t* a,
                                                uint32_t b0, uint32_t b1) {
    asm volatile(
        "mma.sync.aligned.m16n8k16.row.col.f32.f16.f16.f32 "
        "{%0,%1,%2,%3}, {%4,%5,%6,%7}, {%8,%9}, {%0,%1,%2,%3};"
        : "+f"(c[0]), "+f"(c[1]), "+f"(c[2]), "+f"(c[3])
        : "r"(a[0]), "r"(a[1]), "r"(a[2]), "r"(a[3]), "r"(b0), "r"(b1));
}

// ---------------- kernel 3: conv -------------------------------------------
// grid (4 oc-quarter, 64 hpair, 16 n); 256 threads (8 warps), 2 CTAs/SM.
// CTA tile: 64 oc x (2h x 128w). Warp tile: 32 oc x (1h x 64w).
// smem buffer: [4 rows][130 widx][16 ic] halves; widx = w+1.
#define ROWH (130 * 16)               // halves per row
#define BUF_H (4 * ROWH)              // halves per buffer

__global__ void __launch_bounds__(256, 2)
conv_kernel(const float* __restrict__ bias, float* __restrict__ out) {
    __shared__ __half sB[2 * BUF_H];
    __shared__ float s_inv[64], s_b[64];

    const int oq = blockIdx.x;            // oc quarter (0..3)
    const int oh = oq >> 1;               // wfrag oc-half
    const int hbase = blockIdx.y * 2;
    const int n_img = blockIdx.z;
    const int tid = threadIdx.x;
    const int l = tid & 31;
    const int ww = tid >> 5;
    const int warp_m = ww >> 2;           // 0..1 -> 32-oc group
    const int warp_n = ww & 3;
    const int h_sub = warp_n >> 1;
    const int wbase = (warp_n & 1) * 64;

    const float x_max = __uint_as_float(g_xmax_bits);
    const float fx = (x_max > 0.f) ? FXC / x_max : 1.0f;

    // zero both buffers once (w-padding + OOB rows stay zero for all chunks)
    {
        uint4* z = reinterpret_cast<uint4*>(sB);
        const int n16 = (2 * BUF_H * 2) / 16;
        for (int i = tid; i < n16; i += 256) z[i] = make_uint4(0, 0, 0, 0);
    }
    if (tid < 64) {
        s_inv[tid] = 1.0f / (fx * g_fw[oq * 64 + tid]);
        s_b[tid] = __ldg(&bias[oq * 64 + tid]);
    }

    float acc[2][8][4];
#pragma unroll
    for (int a = 0; a < 2; a++)
#pragma unroll
        for (int b = 0; b < 8; b++)
#pragma unroll
            for (int c = 0; c < 4; c++) acc[a][b][c] = 0.f;

    const __half* xT = g_xqT + (size_t)n_img * Hh * Wd * Cc;
    const int st_w = tid >> 1;
    const int st_ich = (tid & 1) * 8;
    const __half* st_g = xT + ((size_t)(hbase - 1) * Wd + st_w) * Cc + st_ich;
    __half* st_s = sB + ((st_w + 1) * 16 + st_ich);
    bool rowok[4];
#pragma unroll
    for (int r4 = 0; r4 < 4; r4++)
        rowok[r4] = (unsigned)(hbase + r4 - 1) < (unsigned)Hh;

    const uint4* wf = reinterpret_cast<const uint4*>(g_wfrag);
    const int mtg_base = (oq & 1) * 4 + warp_m * 2;   // 2 mt tiles per warp

    __syncthreads();
    // stage chunk 0 into buffer 0
    {
        uint4 pf[4];
#pragma unroll
        for (int r4 = 0; r4 < 4; r4++)
            if (rowok[r4])
                pf[r4] = *reinterpret_cast<const uint4*>(st_g + (size_t)r4 * Wd * Cc);
#pragma unroll
        for (int r4 = 0; r4 < 4; r4++)
            if (rowok[r4])
                *reinterpret_cast<uint4*>(st_s + r4 * ROWH) = pf[r4];
    }
    __syncthreads();

    for (int ck = 0; ck < 8; ck++) {
        const int cur = ck & 1;
        const __half* sbuf = sB + cur * BUF_H;

        // prefetch next chunk's x into registers (hidden behind MMA)
        uint4 pf[4];
        if (ck < 7) {
            const __half* gsrc = st_g + (ck + 1) * 16;
#pragma unroll
            for (int r4 = 0; r4 < 4; r4++)
                if (rowok[r4])
                    pf[r4] = *reinterpret_cast<const uint4*>(gsrc + (size_t)r4 * Wd * Cc);
        }

        // A-fragment double buffer (tap-level prefetch)
        uint4 a_buf[2][2];
        {
            const int tile0 = ((oh * 8 + ck) * 9 + 0) * 8 + mtg_base;
#pragma unroll
            for (int mt = 0; mt < 2; mt++)
                a_buf[0][mt] = __ldg(&wf[(tile0 + mt) * 32 + l]);
        }
#pragma unroll
        for (int tap = 0; tap < 9; tap++) {
            const int curA = tap & 1;
            if (tap < 8) {
                const int tileN = ((oh * 8 + ck) * 9 + tap + 1) * 8 + mtg_base;
#pragma unroll
                for (int mt = 0; mt < 2; mt++)
                    a_buf[curA ^ 1][mt] = __ldg(&wf[(tileN + mt) * 32 + l]);
            }
            const int kh = tap / 3, kw = tap - kh * 3;
            const int row4 = h_sub + kh;
            const int widx = wbase + (l >> 2) + kw;
            const __half* bp0 = sbuf + (row4 * 130 + widx) * 16 + 4 * (l & 3);
#pragma unroll
            for (int nt = 0; nt < 8; nt++) {
                const uint2 bv = *reinterpret_cast<const uint2*>(bp0 + nt * 8 * 16);
#pragma unroll
                for (int mt = 0; mt < 2; mt++)
                    mma16816(acc[mt][nt],
                             reinterpret_cast<const uint32_t*>(&a_buf[curA][mt]),
                             bv.x, bv.y);
            }
        }

        if (ck < 7) {
            __half* sdst = sB + (cur ^ 1) * BUF_H + ((st_w + 1) * 16 + st_ich);
#pragma unroll
            for (int r4 = 0; r4 < 4; r4++)
                if (rowok[r4])
                    *reinterpret_cast<uint4*>(sdst + r4 * ROWH) = pf[r4];
        }
        __syncthreads();
    }

    // ---- epilogue: dequant + bias + relu, float2 stores ----
    const int h = hbase + h_sub;
#pragma unroll
    for (int mt = 0; mt < 2; mt++) {
#pragma unroll
        for (int r2 = 0; r2 < 2; r2++) {
            const int ocl = warp_m * 32 + mt * 16 + (l >> 2) + r2 * 8;
            const float inv = s_inv[ocl];
            const float bv = s_b[ocl];
            float* orow =
                out + (((size_t)n_img * Oo + oq * 64 + ocl) * Hh + h) * Wd;
#pragma unroll
            for (int nt = 0; nt < 8; nt++) {
                const int w = wbase + nt * 8 + 2 * (l & 3);
                float2 o2;
                o2.x = fmaxf(fmaf(acc[mt][nt][r2 * 2], inv, bv), 0.f);
                o2.y = fmaxf(fmaf(acc[mt][nt][r2 * 2 + 1], inv, bv), 0.f);
                *reinterpret_cast<float2*>(&orow[w]) = o2;
            }
        }
    }
}

// ---------------- launch ----------------------------------------------------
extern "C" void kernel_launch(void* const* d_in, const int* in_sizes, int n_in,
                              void* d_out, int out_size) {
    const float* x = (const float*)d_in[0];   // [16,128,128,128]
    const float* Wt = (const float*)d_in[1];  // [256,128,3,3]
    const float* b = (const float*)d_in[2];   // [256]
    float* out = (float*)d_out;               // [16,256,128,128]

    const int n4 = (Bn * Cc * Hh * Wd) / 4;
    k1_xmax_prep<<<1024 + Oo, 256>>>((const float4*)x, n4, Wt);
    k2_xq_pack<<<2048 + 576, 256>>>(x);
    k_dummy<<<1, 32>>>();
    dim3 grid(4, 64, Bn);
    conv_kernel<<<grid, 256>>>(b, out);
}